// round 13
// baseline (speedup 1.0000x reference)
#include <cuda_runtime.h>
#include <math.h>
#include <stdint.h>

#define LL 2048
#define NROWS 8192   // B*L
#define QC 64        // chunk length
#define NCHUNK 32    // chunks per batch

// ---------------- scratch (device globals; no runtime allocation) ----------------
static __device__ float g_zx [NROWS * 3088]; // zxbcdt
static __device__ float g_X  [NROWS * 1024]; // silu(conv) x part [row][h*64+r*16+p]
static __device__ float g_BmT[NROWS * 512];  // B^T [row][r*128+n]
static __device__ float g_CmT[NROWS * 512];  // C^T [row][r*128+n]
static __device__ float g_dth[4 * 16 * LL];  // dt  [b,h,t]
static __device__ float g_La [4 * 16 * LL];  // chunk-local cumsum(logdec) [b,h,t]
static __device__ float g_G  [128 * 65536];  // scores [b*32+c][tq*256+sq]
static __device__ float g_P  [2048 * 2048];  // chunk state contrib
static __device__ float g_S  [2048 * 2048];  // chunk-start states
static __device__ float g_g  [NROWS * 1024]; // gated
static __device__ float g_res[NROWS * 512];  // pre-norm residual

// ---------------- tf32 helpers (gscore) --------------------------------------------
__device__ __forceinline__ uint32_t f2tf32(float v) {
    uint32_t r;
    asm("cvt.rna.tf32.f32 %0, %1;" : "=r"(r) : "f"(v));
    return r;
}
__device__ __forceinline__ void split_tf32(float v, float& hi, float& lo) {
    uint32_t h = f2tf32(v);
    hi = __uint_as_float(h);
    float l = v - hi;
    lo = __uint_as_float(f2tf32(l));
}
__device__ __forceinline__ void mma_tf32(float d[4],
                                         uint32_t a0, uint32_t a1, uint32_t a2, uint32_t a3,
                                         uint32_t b0, uint32_t b1) {
    asm volatile(
        "mma.sync.aligned.m16n8k8.row.col.f32.tf32.tf32.f32 "
        "{%0,%1,%2,%3}, {%4,%5,%6,%7}, {%8,%9}, {%0,%1,%2,%3};"
        : "+f"(d[0]), "+f"(d[1]), "+f"(d[2]), "+f"(d[3])
        : "r"(a0), "r"(a1), "r"(a2), "r"(a3), "r"(b0), "r"(b1));
}

// ---------------- bf16 helpers ------------------------------------------------------
__device__ __forceinline__ void bsplit2(float x0, float x1, uint32_t& hi, uint32_t& lo) {
    asm("cvt.rn.bf16x2.f32 %0, %2, %1;" : "=r"(hi) : "f"(x0), "f"(x1));
    const float h0 = __uint_as_float(hi << 16);
    const float h1 = __uint_as_float(hi & 0xffff0000u);
    const float l0 = x0 - h0;
    const float l1 = x1 - h1;
    asm("cvt.rn.bf16x2.f32 %0, %2, %1;" : "=r"(lo) : "f"(l0), "f"(l1));
}
__device__ __forceinline__ void mma_bf16(float d[4],
                                         uint32_t a0, uint32_t a1, uint32_t a2, uint32_t a3,
                                         uint32_t b0, uint32_t b1) {
    asm volatile(
        "mma.sync.aligned.m16n8k16.row.col.f32.bf16.bf16.f32 "
        "{%0,%1,%2,%3}, {%4,%5,%6,%7}, {%8,%9}, {%0,%1,%2,%3};"
        : "+f"(d[0]), "+f"(d[1]), "+f"(d[2]), "+f"(d[3])
        : "r"(a0), "r"(a1), "r"(a2), "r"(a3), "r"(b0), "r"(b1));
}

// ---------------- BF16 3-pass tensor-core GEMM -------------------------------------
template<int Nv, int Kv, bool GUARD, bool ADDRES>
__device__ __forceinline__ void gemm_bf16_body(const float* __restrict__ A,
                                               const float* __restrict__ Bw,
                                               float* __restrict__ C,
                                               const float* __restrict__ Res,
                                               int mbase)
{
    __shared__ __align__(16) uint32_t sA[2][2][8][136];
    __shared__ __align__(16) uint32_t sB[2][2][8][136];

    const int tid   = threadIdx.x;
    const int warp  = tid >> 5;
    const int lane  = tid & 31;
    const int gid   = lane >> 2;
    const int tig   = lane & 3;
    const int warpM = warp & 1;
    const int warpN = warp >> 1;

    const int aRow = tid >> 1;
    const int aK2  = (tid & 1) * 4;
    const int bK2  = tid >> 5;
    const int bCol = (tid & 31) * 4;

    const int nbase = blockIdx.x * 128;
    const float* Ap  = A + (size_t)(mbase + aRow) * Kv + aK2 * 2;
    const float* Bp0 = Bw + (size_t)(2 * bK2) * Nv + nbase + bCol;
    const float* Bp1 = Bp0 + Nv;
    const bool  bOK = (!GUARD) || (nbase + bCol + 3 < Nv);

    float acc[4][4][4];
#pragma unroll
    for (int mt = 0; mt < 4; mt++)
#pragma unroll
        for (int nt = 0; nt < 4; nt++)
#pragma unroll
            for (int i = 0; i < 4; i++) acc[mt][nt][i] = 0.f;

    {
        float4 av0 = *(const float4*)Ap;
        float4 av1 = *(const float4*)(Ap + 4);
        float4 bv0 = bOK ? *(const float4*)Bp0 : make_float4(0.f,0.f,0.f,0.f);
        float4 bv1 = bOK ? *(const float4*)Bp1 : make_float4(0.f,0.f,0.f,0.f);
        uint32_t h, l;
        bsplit2(av0.x, av0.y, h, l); sA[0][0][aK2+0][aRow] = h; sA[0][1][aK2+0][aRow] = l;
        bsplit2(av0.z, av0.w, h, l); sA[0][0][aK2+1][aRow] = h; sA[0][1][aK2+1][aRow] = l;
        bsplit2(av1.x, av1.y, h, l); sA[0][0][aK2+2][aRow] = h; sA[0][1][aK2+2][aRow] = l;
        bsplit2(av1.z, av1.w, h, l); sA[0][0][aK2+3][aRow] = h; sA[0][1][aK2+3][aRow] = l;
        uint32_t hw[4], lw[4];
        bsplit2(bv0.x, bv1.x, hw[0], lw[0]);
        bsplit2(bv0.y, bv1.y, hw[1], lw[1]);
        bsplit2(bv0.z, bv1.z, hw[2], lw[2]);
        bsplit2(bv0.w, bv1.w, hw[3], lw[3]);
        *(uint4*)&sB[0][0][bK2][bCol] = make_uint4(hw[0], hw[1], hw[2], hw[3]);
        *(uint4*)&sB[0][1][bK2][bCol] = make_uint4(lw[0], lw[1], lw[2], lw[3]);
    }
    __syncthreads();

    const int NK = Kv / 16;
    for (int ks = 0; ks < NK; ks++) {
        const int buf = ks & 1;
        float4 av0, av1, bv0, bv1;
        const bool hasNext = (ks + 1 < NK);
        if (hasNext) {
            av0 = *(const float4*)(Ap + (ks + 1) * 16);
            av1 = *(const float4*)(Ap + (ks + 1) * 16 + 4);
            bv0 = bOK ? *(const float4*)(Bp0 + (size_t)(ks + 1) * 16 * Nv)
                      : make_float4(0.f,0.f,0.f,0.f);
            bv1 = bOK ? *(const float4*)(Bp1 + (size_t)(ks + 1) * 16 * Nv)
                      : make_float4(0.f,0.f,0.f,0.f);
        }

        const uint32_t (*Ah)[136] = sA[buf][0];
        const uint32_t (*Al)[136] = sA[buf][1];
        const uint32_t (*Bh)[136] = sB[buf][0];
        const uint32_t (*Bl)[136] = sB[buf][1];

        uint32_t ah[4][4], al[4][4], bh[4][2], bl[4][2];
#pragma unroll
        for (int mt = 0; mt < 4; mt++) {
            const int r = warpM * 64 + mt * 16 + gid;
            ah[mt][0] = Ah[tig    ][r    ];
            ah[mt][1] = Ah[tig    ][r + 8];
            ah[mt][2] = Ah[tig + 4][r    ];
            ah[mt][3] = Ah[tig + 4][r + 8];
            al[mt][0] = Al[tig    ][r    ];
            al[mt][1] = Al[tig    ][r + 8];
            al[mt][2] = Al[tig + 4][r    ];
            al[mt][3] = Al[tig + 4][r + 8];
        }
#pragma unroll
        for (int nt = 0; nt < 4; nt++) {
            const int c = warpN * 32 + nt * 8 + gid;
            bh[nt][0] = Bh[tig    ][c];
            bh[nt][1] = Bh[tig + 4][c];
            bl[nt][0] = Bl[tig    ][c];
            bl[nt][1] = Bl[tig + 4][c];
        }

#pragma unroll
        for (int mt = 0; mt < 4; mt++)
#pragma unroll
            for (int nt = 0; nt < 4; nt++) {
                mma_bf16(acc[mt][nt], ah[mt][0], ah[mt][1], ah[mt][2], ah[mt][3],
                         bh[nt][0], bh[nt][1]);
                mma_bf16(acc[mt][nt], ah[mt][0], ah[mt][1], ah[mt][2], ah[mt][3],
                         bl[nt][0], bl[nt][1]);
                mma_bf16(acc[mt][nt], al[mt][0], al[mt][1], al[mt][2], al[mt][3],
                         bh[nt][0], bh[nt][1]);
            }

        if (hasNext) {
            const int nb = buf ^ 1;
            uint32_t h, l;
            bsplit2(av0.x, av0.y, h, l); sA[nb][0][aK2+0][aRow] = h; sA[nb][1][aK2+0][aRow] = l;
            bsplit2(av0.z, av0.w, h, l); sA[nb][0][aK2+1][aRow] = h; sA[nb][1][aK2+1][aRow] = l;
            bsplit2(av1.x, av1.y, h, l); sA[nb][0][aK2+2][aRow] = h; sA[nb][1][aK2+2][aRow] = l;
            bsplit2(av1.z, av1.w, h, l); sA[nb][0][aK2+3][aRow] = h; sA[nb][1][aK2+3][aRow] = l;
            uint32_t hw[4], lw[4];
            bsplit2(bv0.x, bv1.x, hw[0], lw[0]);
            bsplit2(bv0.y, bv1.y, hw[1], lw[1]);
            bsplit2(bv0.z, bv1.z, hw[2], lw[2]);
            bsplit2(bv0.w, bv1.w, hw[3], lw[3]);
            *(uint4*)&sB[nb][0][bK2][bCol] = make_uint4(hw[0], hw[1], hw[2], hw[3]);
            *(uint4*)&sB[nb][1][bK2][bCol] = make_uint4(lw[0], lw[1], lw[2], lw[3]);
        }
        __syncthreads();
    }

#pragma unroll
    for (int mt = 0; mt < 4; mt++) {
        const int row0 = mbase + warpM * 64 + mt * 16 + gid;
#pragma unroll
        for (int nt = 0; nt < 4; nt++) {
            const int col = nbase + warpN * 32 + nt * 8 + tig * 2;
            if (!GUARD || col < Nv) {
                float2 v0 = make_float2(acc[mt][nt][0], acc[mt][nt][1]);
                float2 v1 = make_float2(acc[mt][nt][2], acc[mt][nt][3]);
                if (ADDRES) {
                    float2 r0 = *(const float2*)(Res + (size_t)row0 * Nv + col);
                    float2 r1 = *(const float2*)(Res + (size_t)(row0 + 8) * Nv + col);
                    v0.x += r0.x; v0.y += r0.y; v1.x += r1.x; v1.y += r1.y;
                }
                *(float2*)(C + (size_t)row0 * Nv + col)       = v0;
                *(float2*)(C + (size_t)(row0 + 8) * Nv + col) = v1;
            }
        }
    }
}

__global__ void __launch_bounds__(256) gemm1_kernel(const float* __restrict__ A,
                                                    const float* __restrict__ W,
                                                    int mrow0)
{
    gemm_bf16_body<3088, 512, true, false>(A, W, g_zx, nullptr,
                                           mrow0 + blockIdx.y * 128);
}

__global__ void __launch_bounds__(256) gemm2_kernel(const float* __restrict__ W,
                                                    const float* __restrict__ Res)
{
    gemm_bf16_body<512, 1024, false, true>(g_g, W, g_res, Res, blockIdx.y * 128);
}

// ---------------- K_G: G = Chat @ Bhat^T per (b,chunk), TF32 3-pass ---------------
__global__ void __launch_bounds__(256) gscore_kernel()
{
    __shared__ __align__(16) float sA[2][2][8][136];
    __shared__ __align__(16) float sB[2][2][8][136];

    const int tid   = threadIdx.x;
    const int warp  = tid >> 5;
    const int lane  = tid & 31;
    const int gid   = lane >> 2;
    const int tig   = lane & 3;
    const int warpM = warp & 1;
    const int warpN = warp >> 1;
    const int ldRow = tid >> 1;
    const int ldCol = (tid & 1) * 4;

    const int bc    = blockIdx.z;
    const int nbase = blockIdx.x * 128;
    const int mbase = blockIdx.y * 128;
    const float* Ap = g_CmT + (size_t)bc * 32768 + (size_t)(mbase + ldRow) * 128 + ldCol;
    const float* Bp = g_BmT + (size_t)bc * 32768 + (size_t)(nbase + ldRow) * 128 + ldCol;
    float* Cp = g_G + (size_t)bc * 65536;

    float acc[4][4][4];
#pragma unroll
    for (int mt = 0; mt < 4; mt++)
#pragma unroll
        for (int nt = 0; nt < 4; nt++)
#pragma unroll
            for (int i = 0; i < 4; i++) acc[mt][nt][i] = 0.f;

    {
        float4 av = *(const float4*)Ap;
        float4 bv = *(const float4*)Bp;
        float h, l;
        split_tf32(av.x, h, l); sA[0][0][ldCol+0][ldRow] = h; sA[0][1][ldCol+0][ldRow] = l;
        split_tf32(av.y, h, l); sA[0][0][ldCol+1][ldRow] = h; sA[0][1][ldCol+1][ldRow] = l;
        split_tf32(av.z, h, l); sA[0][0][ldCol+2][ldRow] = h; sA[0][1][ldCol+2][ldRow] = l;
        split_tf32(av.w, h, l); sA[0][0][ldCol+3][ldRow] = h; sA[0][1][ldCol+3][ldRow] = l;
        split_tf32(bv.x, h, l); sB[0][0][ldCol+0][ldRow] = h; sB[0][1][ldCol+0][ldRow] = l;
        split_tf32(bv.y, h, l); sB[0][0][ldCol+1][ldRow] = h; sB[0][1][ldCol+1][ldRow] = l;
        split_tf32(bv.z, h, l); sB[0][0][ldCol+2][ldRow] = h; sB[0][1][ldCol+2][ldRow] = l;
        split_tf32(bv.w, h, l); sB[0][0][ldCol+3][ldRow] = h; sB[0][1][ldCol+3][ldRow] = l;
    }
    __syncthreads();

    for (int ks = 0; ks < 16; ks++) {
        const int buf = ks & 1;
        float4 av, bv;
        const bool hasNext = (ks + 1 < 16);
        if (hasNext) {
            av = *(const float4*)(Ap + (ks + 1) * 8);
            bv = *(const float4*)(Bp + (ks + 1) * 8);
        }

        const float (*Ah)[136] = sA[buf][0];
        const float (*Al)[136] = sA[buf][1];
        const float (*Bh)[136] = sB[buf][0];
        const float (*Bl)[136] = sB[buf][1];

        uint32_t ah[4][4], al[4][4], bh[4][2], bl[4][2];
#pragma unroll
        for (int mt = 0; mt < 4; mt++) {
            const int r = warpM * 64 + mt * 16 + gid;
            ah[mt][0] = __float_as_uint(Ah[tig    ][r    ]);
            ah[mt][1] = __float_as_uint(Ah[tig    ][r + 8]);
            ah[mt][2] = __float_as_uint(Ah[tig + 4][r    ]);
            ah[mt][3] = __float_as_uint(Ah[tig + 4][r + 8]);
            al[mt][0] = __float_as_uint(Al[tig    ][r    ]);
            al[mt][1] = __float_as_uint(Al[tig    ][r + 8]);
            al[mt][2] = __float_as_uint(Al[tig + 4][r    ]);
            al[mt][3] = __float_as_uint(Al[tig + 4][r + 8]);
        }
#pragma unroll
        for (int nt = 0; nt < 4; nt++) {
            const int c = warpN * 32 + nt * 8 + gid;
            bh[nt][0] = __float_as_uint(Bh[tig    ][c]);
            bh[nt][1] = __float_as_uint(Bh[tig + 4][c]);
            bl[nt][0] = __float_as_uint(Bl[tig    ][c]);
            bl[nt][1] = __float_as_uint(Bl[tig + 4][c]);
        }

#pragma unroll
        for (int mt = 0; mt < 4; mt++)
#pragma unroll
            for (int nt = 0; nt < 4; nt++) {
                mma_tf32(acc[mt][nt], ah[mt][0], ah[mt][1], ah[mt][2], ah[mt][3],
                         bh[nt][0], bh[nt][1]);
                mma_tf32(acc[mt][nt], ah[mt][0], ah[mt][1], ah[mt][2], ah[mt][3],
                         bl[nt][0], bl[nt][1]);
                mma_tf32(acc[mt][nt], al[mt][0], al[mt][1], al[mt][2], al[mt][3],
                         bh[nt][0], bh[nt][1]);
            }

        if (hasNext) {
            const int nb = buf ^ 1;
            float h, l;
            split_tf32(av.x, h, l); sA[nb][0][ldCol+0][ldRow] = h; sA[nb][1][ldCol+0][ldRow] = l;
            split_tf32(av.y, h, l); sA[nb][0][ldCol+1][ldRow] = h; sA[nb][1][ldCol+1][ldRow] = l;
            split_tf32(av.z, h, l); sA[nb][0][ldCol+2][ldRow] = h; sA[nb][1][ldCol+2][ldRow] = l;
            split_tf32(av.w, h, l); sA[nb][0][ldCol+3][ldRow] = h; sA[nb][1][ldCol+3][ldRow] = l;
            split_tf32(bv.x, h, l); sB[nb][0][ldCol+0][ldRow] = h; sB[nb][1][ldCol+0][ldRow] = l;
            split_tf32(bv.y, h, l); sB[nb][0][ldCol+1][ldRow] = h; sB[nb][1][ldCol+1][ldRow] = l;
            split_tf32(bv.z, h, l); sB[nb][0][ldCol+2][ldRow] = h; sB[nb][1][ldCol+2][ldRow] = l;
            split_tf32(bv.w, h, l); sB[nb][0][ldCol+3][ldRow] = h; sB[nb][1][ldCol+3][ldRow] = l;
        }
        __syncthreads();
    }

#pragma unroll
    for (int mt = 0; mt < 4; mt++) {
        const int row0 = mbase + warpM * 64 + mt * 16 + gid;
#pragma unroll
        for (int nt = 0; nt < 4; nt++) {
            const int col = nbase + warpN * 32 + nt * 8 + tig * 2;
            *(float2*)(Cp + (size_t)row0 * 256 + col)       = make_float2(acc[mt][nt][0], acc[mt][nt][1]);
            *(float2*)(Cp + (size_t)(row0 + 8) * 256 + col) = make_float2(acc[mt][nt][2], acc[mt][nt][3]);
        }
    }
}

// ---------------- conv1d tiled (8 t/thread) + silu + split + fused dt -------------
__global__ void conv_kernel(const float* __restrict__ conv_w,
                            const float* __restrict__ conv_b,
                            const float* __restrict__ dt_bias,
                            const float* __restrict__ A_log)
{
    const int idx = blockIdx.x * blockDim.x + threadIdx.x; // [0, 1024*2048)
    const int c   = idx & 2047;
    const int grp = idx >> 11;          // 0..1023
    const int b   = grp >> 8;           // 256 t-groups per batch
    const int t0  = (grp & 255) * 8;
    const int row0 = b * LL + t0;

    const float4 wv = *(const float4*)(conv_w + c * 4);
    const float bias = conv_b[c];

    float v[11];
#pragma unroll
    for (int j = 0; j < 11; j++) {
        const int t = t0 + j - 3;
        v[j] = (t >= 0) ? g_zx[(size_t)(b * LL + t) * 3088 + 1024 + c] : 0.f;
    }

#pragma unroll
    for (int j = 0; j < 8; j++) {
        float acc = bias;
        acc = fmaf(v[j],     wv.x, acc);
        acc = fmaf(v[j + 1], wv.y, acc);
        acc = fmaf(v[j + 2], wv.z, acc);
        acc = fmaf(v[j + 3], wv.w, acc);
        const float val = acc / (1.f + __expf(-acc));  // silu
        const int row = row0 + j;
        if (c < 1024)       g_X[(size_t)row * 1024 + c] = val;
        else if (c < 1536) {
            const int i = c - 1024;
            g_BmT[(size_t)row * 512 + (i & 3) * 128 + (i >> 2)] = val;
        } else {
            const int i = c - 1536;
            g_CmT[(size_t)row * 512 + (i & 3) * 128 + (i >> 2)] = val;
        }
    }

    // fused dt/logdec for heads (threads c<16 handle head h=c)
    if (c < 16) {
        const float ex = __expf(A_log[c]);
        const float db = dt_bias[c];
#pragma unroll
        for (int j = 0; j < 8; j++) {
            const int row = row0 + j;
            const float x = g_zx[(size_t)row * 3088 + 3072 + c] + db;
            const float dt = (x > 20.f) ? x : log1pf(__expf(x));
            const size_t o = ((size_t)b * 16 + c) * LL + (t0 + j);
            g_dth[o] = dt;
            g_La [o] = -ex * dt;
        }
    }
}

// ---------------- chunk-local inclusive cumsum of logdec --------------------------
__global__ void __launch_bounds__(256) cumsum_kernel()
{
    const int gw   = blockIdx.x * 8 + (threadIdx.x >> 5);
    const int lane = threadIdx.x & 31;
    const int c    = gw & (NCHUNK - 1);
    const int bh   = gw >> 5;
    float* base = g_La + (size_t)bh * LL + c * QC;
    float v0 = base[2 * lane];
    float v1 = base[2 * lane + 1];
    float s  = v0 + v1;
#pragma unroll
    for (int o = 1; o < 32; o <<= 1) {
        float other = __shfl_up_sync(0xffffffffu, s, o);
        if (lane >= o) s += other;
    }
    const float excl = s - (v0 + v1);
    base[2 * lane]     = excl + v0;
    base[2 * lane + 1] = excl + v0 + v1;
}

// ---------------- K_P: per-chunk state contribution -------------------------------
// thread: n = tid&127 (warp lanes -> consecutive n, coalesced B loads), ph = tid>>7.
__global__ void __launch_bounds__(256) pstate_kernel()
{
    const int bx = blockIdx.x;
    const int hh = bx & 15;
    const int cc = (bx >> 4) & (NCHUNK - 1);
    const int bb = bx >> 9;
    const int tid = threadIdx.x;

    __shared__ __align__(16) float sX[256][16];
    __shared__ float sW[64];

    const int brow = bb * LL + cc * QC;
    {
        const int s = tid >> 2, q = tid & 3;
        const float4* src = (const float4*)(g_X + (size_t)(brow + s) * 1024 + hh * 64 + q * 16);
        float4* dst = (float4*)&sX[(s << 2) | q][0];
#pragma unroll
        for (int i = 0; i < 4; i++) dst[i] = src[i];
    }
    if (tid < 64) {
        const float* Lab = g_La  + ((size_t)bb * 16 + hh) * LL + cc * QC;
        const float* Dtb = g_dth + ((size_t)bb * 16 + hh) * LL + cc * QC;
        sW[tid] = __expf(Lab[63] - Lab[tid]) * Dtb[tid];
    }
    __syncthreads();

    const int n  = tid & 127;
    const int ph = tid >> 7;
    float a[8];
#pragma unroll
    for (int i = 0; i < 8; i++) a[i] = 0.f;

    const float* Bb = g_BmT + (size_t)brow * 512 + n;
    for (int s = 0; s < QC; s++) {
        const float w = sW[s];
#pragma unroll
        for (int rp = 0; rp < 4; rp++) {
            const float bw = __ldg(Bb + (size_t)s * 512 + rp * 128) * w;
            const float4 x0 = *(const float4*)&sX[s * 4 + rp][ph * 8];
            const float4 x1 = *(const float4*)&sX[s * 4 + rp][ph * 8 + 4];
            a[0] = fmaf(bw, x0.x, a[0]); a[1] = fmaf(bw, x0.y, a[1]);
            a[2] = fmaf(bw, x0.z, a[2]); a[3] = fmaf(bw, x0.w, a[3]);
            a[4] = fmaf(bw, x1.x, a[4]); a[5] = fmaf(bw, x1.y, a[5]);
            a[6] = fmaf(bw, x1.z, a[6]); a[7] = fmaf(bw, x1.w, a[7]);
        }
    }
    float* Pp = g_P + (size_t)bx * 2048 + n * 16 + ph * 8;
    *(float4*)Pp       = make_float4(a[0], a[1], a[2], a[3]);
    *(float4*)(Pp + 4) = make_float4(a[4], a[5], a[6], a[7]);
}

// ---------------- K_carry: sequential chunk-state chain ---------------------------
__global__ void __launch_bounds__(256) carry_kernel()
{
    const int bx = blockIdx.x;
    const int bb = bx >> 4;
    const int hh = bx & 15;
    const int off = threadIdx.x * 8;
    const float* Lab = g_La + ((size_t)bb * 16 + hh) * LL;

    float4 s0 = make_float4(0.f,0.f,0.f,0.f);
    float4 s1 = make_float4(0.f,0.f,0.f,0.f);
    for (int c = 0; c < NCHUNK; c++) {
        const size_t slot = ((size_t)(bb * NCHUNK + c) * 16 + hh) * 2048 + off;
        *(float4*)(g_S + slot)     = s0;
        *(float4*)(g_S + slot + 4) = s1;
        const float ef = __expf(Lab[c * QC + 63]);
        const float4 p0 = *(const float4*)(g_P + slot);
        const float4 p1 = *(const float4*)(g_P + slot + 4);
        s0.x = fmaf(ef, s0.x, p0.x); s0.y = fmaf(ef, s0.y, p0.y);
        s0.z = fmaf(ef, s0.z, p0.z); s0.w = fmaf(ef, s0.w, p0.w);
        s1.x = fmaf(ef, s1.x, p1.x); s1.y = fmaf(ef, s1.y, p1.y);
        s1.z = fmaf(ef, s1.z, p1.z); s1.w = fmaf(ef, s1.w, p1.w);
    }
}

// ---------------- K_y: y = inter + intra, fused D_skip + z-gate -------------------
__global__ void __launch_bounds__(256) yout_kernel(const float* __restrict__ D_skip)
{
    const int bx = blockIdx.x;
    const int hh = bx & 15;
    const int cc = (bx >> 4) & (NCHUNK - 1);
    const int bb = bx >> 9;
    const int tid = threadIdx.x;
    const int t = tid >> 2;
    const int r = tid & 3;

    __shared__ __align__(16) float sX[256][16];
    __shared__ __align__(16) float sS[128][16];
    __shared__ float sLa[64], sDt[64];

    const int brow = bb * LL + cc * QC;
    {
        const int s = tid >> 2, q = tid & 3;
        const float4* src = (const float4*)(g_X + (size_t)(brow + s) * 1024 + hh * 64 + q * 16);
        float4* dst = (float4*)&sX[(s << 2) | q][0];
#pragma unroll
        for (int i = 0; i < 4; i++) dst[i] = src[i];
    }
    {
        const float4* src = (const float4*)(g_S + (size_t)bx * 2048 + tid * 8);
        float4* dst = (float4*)(&sS[0][0] + tid * 8);
        dst[0] = src[0]; dst[1] = src[1];
    }
    if (tid < 64) {
        sLa[tid] = g_La [((size_t)bb * 16 + hh) * LL + cc * QC + tid];
        sDt[tid] = g_dth[((size_t)bb * 16 + hh) * LL + cc * QC + tid];
    }
    __syncthreads();

    float acc[16];
#pragma unroll
    for (int i = 0; i < 16; i++) acc[i] = 0.f;

    // inter-chunk: (Chat @ S_start) * exp(La[t])
    const float4* crow = (const float4*)(g_CmT + (size_t)(brow + t) * 512 + r * 128);
    for (int nq = 0; nq < 32; nq++) {
        const float4 cv = __ldg(crow + nq);
#pragma unroll
        for (int j = 0; j < 4; j++) {
            const float cn = (j == 0) ? cv.x : (j == 1) ? cv.y : (j == 2) ? cv.z : cv.w;
            const float* sr = &sS[nq * 4 + j][0];
#pragma unroll
            for (int p = 0; p < 16; p++) acc[p] = fmaf(cn, sr[p], acc[p]);
        }
    }
    const float lat = sLa[t];
    const float einter = __expf(lat);
#pragma unroll
    for (int p = 0; p < 16; p++) acc[p] *= einter;

    // intra-chunk
    const float4* Gp = (const float4*)(g_G + (size_t)(bb * NCHUNK + cc) * 65536 + (size_t)tid * 256);
    for (int s = 0; s <= t; s++) {
        const float w = __expf(lat - sLa[s]) * sDt[s];
        const float4 gv = __ldg(Gp + s);
        const float g0 = gv.x * w, g1 = gv.y * w, g2 = gv.z * w, g3 = gv.w * w;
        const float* x0 = &sX[s * 4 + 0][0];
        const float* x1 = &sX[s * 4 + 1][0];
        const float* x2 = &sX[s * 4 + 2][0];
        const float* x3 = &sX[s * 4 + 3][0];
#pragma unroll
        for (int p = 0; p < 16; p++) {
            float v = fmaf(g0, x0[p], acc[p]);
            v = fmaf(g1, x1[p], v);
            v = fmaf(g2, x2[p], v);
            acc[p] = fmaf(g3, x3[p], v);
        }
    }

    // epilogue
    const float dsk = D_skip[hh];
    const int row = brow + t;
    const float* xv = &sX[tid][0];
    float* go = g_g + (size_t)row * 1024 + hh * 64 + r * 16;
    const float* zp = g_zx + (size_t)row * 3088 + hh * 64 + r * 16;
#pragma unroll
    for (int p = 0; p < 16; p++) {
        const float y = fmaf(xv[p], dsk, acc[p]);
        const float z = zp[p];
        go[p] = y * (z / (1.f + __expf(-z)));
    }
}

// ---------------- RMSNorm ---------------------------------------------------------
__global__ void __launch_bounds__(256) rms_kernel(float* __restrict__ out)
{
    const int warp = threadIdx.x >> 5;
    const int lane = threadIdx.x & 31;
    const int row  = blockIdx.x * 8 + warp;
    const float* r = g_res + (size_t)row * 512;
    float v[16];
    float ss = 0.f;
#pragma unroll
    for (int i = 0; i < 16; i++) { v[i] = r[lane + i * 32]; ss = fmaf(v[i], v[i], ss); }
#pragma unroll
    for (int o = 16; o >= 1; o >>= 1) ss += __shfl_xor_sync(0xffffffffu, ss, o);
    const float sc = rsqrtf(ss * (1.f / 512.f) + 1e-5f);
    float* o = out + (size_t)row * 512;
#pragma unroll
    for (int i = 0; i < 16; i++) o[lane + i * 32] = v[i] * sc;
}

// ---------------- launch ----------------------------------------------------------
extern "C" void kernel_launch(void* const* d_in, const int* in_sizes, int n_in,
                              void* d_out, int out_size)
{
    const float* hs      = (const float*)d_in[0];
    const float* W_in    = (const float*)d_in[1];
    const float* conv_w  = (const float*)d_in[2];
    const float* conv_b  = (const float*)d_in[3];
    const float* dt_bias = (const float*)d_in[4];
    const float* A_log   = (const float*)d_in[5];
    const float* D_skip  = (const float*)d_in[6];
    const float* W_out   = (const float*)d_in[7];
    float* out = (float*)d_out;

    // gemm1 split into 4 slices (slice 4 lands in the ncu capture slot)
    gemm1_kernel<<<dim3(25, 16), 256>>>(hs, W_in, 0);
    gemm1_kernel<<<dim3(25, 16), 256>>>(hs, W_in, 2048);
    gemm1_kernel<<<dim3(25, 16), 256>>>(hs, W_in, 4096);
    gemm1_kernel<<<dim3(25, 16), 256>>>(hs, W_in, 6144);
    conv_kernel<<<NROWS / 8 * 2048 / 256, 256>>>(conv_w, conv_b, dt_bias, A_log);
    cumsum_kernel<<<256, 256>>>();
    gscore_kernel<<<dim3(2, 2, 128), 256>>>();
    pstate_kernel<<<2048, 256>>>();
    carry_kernel<<<64, 256>>>();
    yout_kernel<<<2048, 256>>>(D_skip);
    gemm2_kernel<<<dim3(4, 64), 256>>>(W_out, hs);
    rms_kernel<<<NROWS / 8, 256>>>(out);
}

// round 14
// speedup vs baseline: 1.0635x; 1.0635x over previous
#include <cuda_runtime.h>
#include <math.h>
#include <stdint.h>

#define LL 2048
#define NROWS 8192   // B*L
#define QC 64        // chunk length
#define NCHUNK 32    // chunks per batch

// ---------------- scratch (device globals; no runtime allocation) ----------------
static __device__ float g_zx [NROWS * 3088]; // zxbcdt
static __device__ float g_X  [NROWS * 1024]; // silu(conv) x part [row][h*64+r*16+p]
static __device__ float g_BmT[NROWS * 512];  // B^T [row][r*128+n]
static __device__ float g_CmT[NROWS * 512];  // C^T [row][r*128+n]
static __device__ float g_dth[4 * 16 * LL];  // dt  [b,h,t]
static __device__ float g_La [4 * 16 * LL];  // chunk-local cumsum(logdec) [b,h,t]
static __device__ float g_G  [128 * 65536];  // scores [b*32+c][tq*256+sq]
static __device__ float g_P  [2048 * 2048];  // chunk state contrib
static __device__ float g_S  [2048 * 2048];  // chunk-start states
static __device__ float g_g  [NROWS * 1024]; // gated
static __device__ float g_res[NROWS * 512];  // pre-norm residual

// ---------------- tf32 helpers (gscore) --------------------------------------------
__device__ __forceinline__ uint32_t f2tf32(float v) {
    uint32_t r;
    asm("cvt.rna.tf32.f32 %0, %1;" : "=r"(r) : "f"(v));
    return r;
}
__device__ __forceinline__ void split_tf32(float v, float& hi, float& lo) {
    uint32_t h = f2tf32(v);
    hi = __uint_as_float(h);
    float l = v - hi;
    lo = __uint_as_float(f2tf32(l));
}
__device__ __forceinline__ void mma_tf32(float d[4],
                                         uint32_t a0, uint32_t a1, uint32_t a2, uint32_t a3,
                                         uint32_t b0, uint32_t b1) {
    asm volatile(
        "mma.sync.aligned.m16n8k8.row.col.f32.tf32.tf32.f32 "
        "{%0,%1,%2,%3}, {%4,%5,%6,%7}, {%8,%9}, {%0,%1,%2,%3};"
        : "+f"(d[0]), "+f"(d[1]), "+f"(d[2]), "+f"(d[3])
        : "r"(a0), "r"(a1), "r"(a2), "r"(a3), "r"(b0), "r"(b1));
}

// ---------------- bf16 helpers ------------------------------------------------------
__device__ __forceinline__ void bsplit2(float x0, float x1, uint32_t& hi, uint32_t& lo) {
    asm("cvt.rn.bf16x2.f32 %0, %2, %1;" : "=r"(hi) : "f"(x0), "f"(x1));
    const float h0 = __uint_as_float(hi << 16);
    const float h1 = __uint_as_float(hi & 0xffff0000u);
    const float l0 = x0 - h0;
    const float l1 = x1 - h1;
    asm("cvt.rn.bf16x2.f32 %0, %2, %1;" : "=r"(lo) : "f"(l0), "f"(l1));
}
__device__ __forceinline__ void mma_bf16(float d[4],
                                         uint32_t a0, uint32_t a1, uint32_t a2, uint32_t a3,
                                         uint32_t b0, uint32_t b1) {
    asm volatile(
        "mma.sync.aligned.m16n8k16.row.col.f32.bf16.bf16.f32 "
        "{%0,%1,%2,%3}, {%4,%5,%6,%7}, {%8,%9}, {%0,%1,%2,%3};"
        : "+f"(d[0]), "+f"(d[1]), "+f"(d[2]), "+f"(d[3])
        : "r"(a0), "r"(a1), "r"(a2), "r"(a3), "r"(b0), "r"(b1));
}
__device__ __forceinline__ void ldsm_x4(uint32_t& r0, uint32_t& r1, uint32_t& r2, uint32_t& r3,
                                        uint32_t addr) {
    asm volatile("ldmatrix.sync.aligned.m8n8.x4.shared.b16 {%0,%1,%2,%3}, [%4];"
                 : "=r"(r0), "=r"(r1), "=r"(r2), "=r"(r3) : "r"(addr));
}
__device__ __forceinline__ void ldsm_x2_t(uint32_t& r0, uint32_t& r1, uint32_t addr) {
    asm volatile("ldmatrix.sync.aligned.m8n8.x2.trans.shared.b16 {%0,%1}, [%2];"
                 : "=r"(r0), "=r"(r1) : "r"(addr));
}

// ---------------- BF16 3-pass GEMM with ldmatrix fragment loads --------------------
// CTA 128x128, 8 warps (2M x 4N). k-slab 16/stage.
// sA: [buf][hi/lo][128 rows x 12 words] (16 bf16 + pad; 48B stride -> ldmatrix banks 12i mod 32, conflict-free)
// sB: [buf][hi/lo][16 k x 68 words] (128 bf16 n-contiguous + pad; 272B stride -> banks 4i, conflict-free)
template<int Nv, int Kv, bool GUARD, bool ADDRES>
__device__ __forceinline__ void gemm_bf16_body(const float* __restrict__ A,
                                               const float* __restrict__ Bw,
                                               float* __restrict__ C,
                                               const float* __restrict__ Res,
                                               int mbase)
{
    __shared__ __align__(16) uint32_t sA[2][2][128 * 12];
    __shared__ __align__(16) uint32_t sB[2][2][16 * 68];

    const int tid   = threadIdx.x;
    const int warp  = tid >> 5;
    const int lane  = tid & 31;
    const int warpM = warp & 1;
    const int warpN = warp >> 1;

    // loader geometry
    const int aRow  = tid >> 1;
    const int aHalf = tid & 1;          // k block 0..7 or 8..15
    const int bK2   = tid >> 5;         // k-pair row (2 rows per warp-group of loaders)
    const int bCol  = (tid & 31) * 4;

    const int nbase = blockIdx.x * 128;
    const float* Ap  = A + (size_t)(mbase + aRow) * Kv + aHalf * 8;
    const float* Bp0 = Bw + (size_t)(2 * bK2) * Nv + nbase + bCol;
    const float* Bp1 = Bp0 + Nv;
    const bool  bOK = (!GUARD) || (nbase + bCol + 3 < Nv);

    // ldmatrix lane geometry
    const int aLRow = (lane & 7) + ((lane >> 3) & 1) * 8;  // row within 16
    const int aLK   = (lane >> 4) * 16;                    // k byte offset 0/16
    const int bLRow = (lane & 7) + ((lane >> 3) & 1) * 8;  // k row (lanes<16 used)

    uint32_t aBase[2][2], bBase[2][2];
#pragma unroll
    for (int bu = 0; bu < 2; bu++)
#pragma unroll
        for (int hf = 0; hf < 2; hf++) {
            aBase[bu][hf] = (uint32_t)__cvta_generic_to_shared(&sA[bu][hf][0]);
            bBase[bu][hf] = (uint32_t)__cvta_generic_to_shared(&sB[bu][hf][0]);
        }

    float acc[4][4][4];
#pragma unroll
    for (int mt = 0; mt < 4; mt++)
#pragma unroll
        for (int nt = 0; nt < 4; nt++)
#pragma unroll
            for (int i = 0; i < 4; i++) acc[mt][nt][i] = 0.f;

#define STORE_A(bu, av0, av1) do { \
        uint32_t h0,l0,h1,l1,h2,l2,h3,l3; \
        bsplit2((av0).x,(av0).y,h0,l0); bsplit2((av0).z,(av0).w,h1,l1); \
        bsplit2((av1).x,(av1).y,h2,l2); bsplit2((av1).z,(av1).w,h3,l3); \
        const uint32_t off = aRow * 12 + aHalf * 4; \
        *(uint4*)&sA[bu][0][off] = make_uint4(h0,h1,h2,h3); \
        *(uint4*)&sA[bu][1][off] = make_uint4(l0,l1,l2,l3); \
    } while (0)
#define STORE_B(bu, bv0, bv1) do { \
        uint32_t h0,l0,h1,l1,h2,l2,h3,l3; \
        bsplit2((bv0).x,(bv0).y,h0,l0); bsplit2((bv0).z,(bv0).w,h1,l1); \
        bsplit2((bv1).x,(bv1).y,h2,l2); bsplit2((bv1).z,(bv1).w,h3,l3); \
        const uint32_t off0 = (2 * bK2) * 68 + (bCol >> 1); \
        *(uint2*)&sB[bu][0][off0]      = make_uint2(h0,h1); \
        *(uint2*)&sB[bu][1][off0]      = make_uint2(l0,l1); \
        *(uint2*)&sB[bu][0][off0 + 68] = make_uint2(h2,h3); \
        *(uint2*)&sB[bu][1][off0 + 68] = make_uint2(l2,l3); \
    } while (0)

    {
        float4 av0 = *(const float4*)Ap;
        float4 av1 = *(const float4*)(Ap + 4);
        float4 bv0 = bOK ? *(const float4*)Bp0 : make_float4(0.f,0.f,0.f,0.f);
        float4 bv1 = bOK ? *(const float4*)Bp1 : make_float4(0.f,0.f,0.f,0.f);
        STORE_A(0, av0, av1);
        STORE_B(0, bv0, bv1);
    }
    __syncthreads();

    const int NK = Kv / 16;
    for (int ks = 0; ks < NK; ks++) {
        const int buf = ks & 1;
        float4 av0, av1, bv0, bv1;
        const bool hasNext = (ks + 1 < NK);
        if (hasNext) {
            av0 = *(const float4*)(Ap + (ks + 1) * 16);
            av1 = *(const float4*)(Ap + (ks + 1) * 16 + 4);
            bv0 = bOK ? *(const float4*)(Bp0 + (size_t)(ks + 1) * 16 * Nv)
                      : make_float4(0.f,0.f,0.f,0.f);
            bv1 = bOK ? *(const float4*)(Bp1 + (size_t)(ks + 1) * 16 * Nv)
                      : make_float4(0.f,0.f,0.f,0.f);
        }

        // ---- fragments via ldmatrix ----
        uint32_t ah[4][4], al[4][4], bh[4][2], bl[4][2];
#pragma unroll
        for (int mt = 0; mt < 4; mt++) {
            const uint32_t rb = (warpM * 64 + mt * 16 + aLRow) * 48 + aLK;
            ldsm_x4(ah[mt][0], ah[mt][1], ah[mt][2], ah[mt][3], aBase[buf][0] + rb);
            ldsm_x4(al[mt][0], al[mt][1], al[mt][2], al[mt][3], aBase[buf][1] + rb);
        }
#pragma unroll
        for (int nt = 0; nt < 4; nt++) {
            const uint32_t rb = bLRow * 272 + (warpN * 32 + nt * 8) * 2;
            ldsm_x2_t(bh[nt][0], bh[nt][1], bBase[buf][0] + rb);
            ldsm_x2_t(bl[nt][0], bl[nt][1], bBase[buf][1] + rb);
        }

        // ---- 3-pass mma ----
#pragma unroll
        for (int mt = 0; mt < 4; mt++)
#pragma unroll
            for (int nt = 0; nt < 4; nt++) {
                mma_bf16(acc[mt][nt], ah[mt][0], ah[mt][1], ah[mt][2], ah[mt][3],
                         bh[nt][0], bh[nt][1]);
                mma_bf16(acc[mt][nt], ah[mt][0], ah[mt][1], ah[mt][2], ah[mt][3],
                         bl[nt][0], bl[nt][1]);
                mma_bf16(acc[mt][nt], al[mt][0], al[mt][1], al[mt][2], al[mt][3],
                         bh[nt][0], bh[nt][1]);
            }

        if (hasNext) {
            const int nb = buf ^ 1;
            STORE_A(nb, av0, av1);
            STORE_B(nb, bv0, bv1);
        }
        __syncthreads();
    }
#undef STORE_A
#undef STORE_B

    const int gid = lane >> 2;
    const int tig = lane & 3;
#pragma unroll
    for (int mt = 0; mt < 4; mt++) {
        const int row0 = mbase + warpM * 64 + mt * 16 + gid;
#pragma unroll
        for (int nt = 0; nt < 4; nt++) {
            const int col = nbase + warpN * 32 + nt * 8 + tig * 2;
            if (!GUARD || col < Nv) {
                float2 v0 = make_float2(acc[mt][nt][0], acc[mt][nt][1]);
                float2 v1 = make_float2(acc[mt][nt][2], acc[mt][nt][3]);
                if (ADDRES) {
                    float2 r0 = *(const float2*)(Res + (size_t)row0 * Nv + col);
                    float2 r1 = *(const float2*)(Res + (size_t)(row0 + 8) * Nv + col);
                    v0.x += r0.x; v0.y += r0.y; v1.x += r1.x; v1.y += r1.y;
                }
                *(float2*)(C + (size_t)row0 * Nv + col)       = v0;
                *(float2*)(C + (size_t)(row0 + 8) * Nv + col) = v1;
            }
        }
    }
}

__global__ void __launch_bounds__(256) gemm1_kernel(const float* __restrict__ A,
                                                    const float* __restrict__ W)
{
    gemm_bf16_body<3088, 512, true, false>(A, W, g_zx, nullptr, blockIdx.y * 128);
}

__global__ void __launch_bounds__(256) gemm2_kernel(const float* __restrict__ W,
                                                    const float* __restrict__ Res)
{
    gemm_bf16_body<512, 1024, false, true>(g_g, W, g_res, Res, blockIdx.y * 128);
}

// ---------------- K_G: G = Chat @ Bhat^T per (b,chunk), TF32 3-pass ---------------
__global__ void __launch_bounds__(256) gscore_kernel()
{
    __shared__ __align__(16) float sA[2][2][8][136];
    __shared__ __align__(16) float sB[2][2][8][136];

    const int tid   = threadIdx.x;
    const int warp  = tid >> 5;
    const int lane  = tid & 31;
    const int gid   = lane >> 2;
    const int tig   = lane & 3;
    const int warpM = warp & 1;
    const int warpN = warp >> 1;
    const int ldRow = tid >> 1;
    const int ldCol = (tid & 1) * 4;

    const int bc    = blockIdx.z;
    const int nbase = blockIdx.x * 128;
    const int mbase = blockIdx.y * 128;
    const float* Ap = g_CmT + (size_t)bc * 32768 + (size_t)(mbase + ldRow) * 128 + ldCol;
    const float* Bp = g_BmT + (size_t)bc * 32768 + (size_t)(nbase + ldRow) * 128 + ldCol;
    float* Cp = g_G + (size_t)bc * 65536;

    float acc[4][4][4];
#pragma unroll
    for (int mt = 0; mt < 4; mt++)
#pragma unroll
        for (int nt = 0; nt < 4; nt++)
#pragma unroll
            for (int i = 0; i < 4; i++) acc[mt][nt][i] = 0.f;

    {
        float4 av = *(const float4*)Ap;
        float4 bv = *(const float4*)Bp;
        float h, l;
        split_tf32(av.x, h, l); sA[0][0][ldCol+0][ldRow] = h; sA[0][1][ldCol+0][ldRow] = l;
        split_tf32(av.y, h, l); sA[0][0][ldCol+1][ldRow] = h; sA[0][1][ldCol+1][ldRow] = l;
        split_tf32(av.z, h, l); sA[0][0][ldCol+2][ldRow] = h; sA[0][1][ldCol+2][ldRow] = l;
        split_tf32(av.w, h, l); sA[0][0][ldCol+3][ldRow] = h; sA[0][1][ldCol+3][ldRow] = l;
        split_tf32(bv.x, h, l); sB[0][0][ldCol+0][ldRow] = h; sB[0][1][ldCol+0][ldRow] = l;
        split_tf32(bv.y, h, l); sB[0][0][ldCol+1][ldRow] = h; sB[0][1][ldCol+1][ldRow] = l;
        split_tf32(bv.z, h, l); sB[0][0][ldCol+2][ldRow] = h; sB[0][1][ldCol+2][ldRow] = l;
        split_tf32(bv.w, h, l); sB[0][0][ldCol+3][ldRow] = h; sB[0][1][ldCol+3][ldRow] = l;
    }
    __syncthreads();

    for (int ks = 0; ks < 16; ks++) {
        const int buf = ks & 1;
        float4 av, bv;
        const bool hasNext = (ks + 1 < 16);
        if (hasNext) {
            av = *(const float4*)(Ap + (ks + 1) * 8);
            bv = *(const float4*)(Bp + (ks + 1) * 8);
        }

        const float (*Ah)[136] = sA[buf][0];
        const float (*Al)[136] = sA[buf][1];
        const float (*Bh)[136] = sB[buf][0];
        const float (*Bl)[136] = sB[buf][1];

        uint32_t ah[4][4], al[4][4], bh[4][2], bl[4][2];
#pragma unroll
        for (int mt = 0; mt < 4; mt++) {
            const int r = warpM * 64 + mt * 16 + gid;
            ah[mt][0] = __float_as_uint(Ah[tig    ][r    ]);
            ah[mt][1] = __float_as_uint(Ah[tig    ][r + 8]);
            ah[mt][2] = __float_as_uint(Ah[tig + 4][r    ]);
            ah[mt][3] = __float_as_uint(Ah[tig + 4][r + 8]);
            al[mt][0] = __float_as_uint(Al[tig    ][r    ]);
            al[mt][1] = __float_as_uint(Al[tig    ][r + 8]);
            al[mt][2] = __float_as_uint(Al[tig + 4][r    ]);
            al[mt][3] = __float_as_uint(Al[tig + 4][r + 8]);
        }
#pragma unroll
        for (int nt = 0; nt < 4; nt++) {
            const int c = warpN * 32 + nt * 8 + gid;
            bh[nt][0] = __float_as_uint(Bh[tig    ][c]);
            bh[nt][1] = __float_as_uint(Bh[tig + 4][c]);
            bl[nt][0] = __float_as_uint(Bl[tig    ][c]);
            bl[nt][1] = __float_as_uint(Bl[tig + 4][c]);
        }

#pragma unroll
        for (int mt = 0; mt < 4; mt++)
#pragma unroll
            for (int nt = 0; nt < 4; nt++) {
                mma_tf32(acc[mt][nt], ah[mt][0], ah[mt][1], ah[mt][2], ah[mt][3],
                         bh[nt][0], bh[nt][1]);
                mma_tf32(acc[mt][nt], ah[mt][0], ah[mt][1], ah[mt][2], ah[mt][3],
                         bl[nt][0], bl[nt][1]);
                mma_tf32(acc[mt][nt], al[mt][0], al[mt][1], al[mt][2], al[mt][3],
                         bh[nt][0], bh[nt][1]);
            }

        if (hasNext) {
            const int nb = buf ^ 1;
            float h, l;
            split_tf32(av.x, h, l); sA[nb][0][ldCol+0][ldRow] = h; sA[nb][1][ldCol+0][ldRow] = l;
            split_tf32(av.y, h, l); sA[nb][0][ldCol+1][ldRow] = h; sA[nb][1][ldCol+1][ldRow] = l;
            split_tf32(av.z, h, l); sA[nb][0][ldCol+2][ldRow] = h; sA[nb][1][ldCol+2][ldRow] = l;
            split_tf32(av.w, h, l); sA[nb][0][ldCol+3][ldRow] = h; sA[nb][1][ldCol+3][ldRow] = l;
            split_tf32(bv.x, h, l); sB[nb][0][ldCol+0][ldRow] = h; sB[nb][1][ldCol+0][ldRow] = l;
            split_tf32(bv.y, h, l); sB[nb][0][ldCol+1][ldRow] = h; sB[nb][1][ldCol+1][ldRow] = l;
            split_tf32(bv.z, h, l); sB[nb][0][ldCol+2][ldRow] = h; sB[nb][1][ldCol+2][ldRow] = l;
            split_tf32(bv.w, h, l); sB[nb][0][ldCol+3][ldRow] = h; sB[nb][1][ldCol+3][ldRow] = l;
        }
        __syncthreads();
    }

#pragma unroll
    for (int mt = 0; mt < 4; mt++) {
        const int row0 = mbase + warpM * 64 + mt * 16 + gid;
#pragma unroll
        for (int nt = 0; nt < 4; nt++) {
            const int col = nbase + warpN * 32 + nt * 8 + tig * 2;
            *(float2*)(Cp + (size_t)row0 * 256 + col)       = make_float2(acc[mt][nt][0], acc[mt][nt][1]);
            *(float2*)(Cp + (size_t)(row0 + 8) * 256 + col) = make_float2(acc[mt][nt][2], acc[mt][nt][3]);
        }
    }
}

// ---------------- conv1d tiled (8 t/thread) + silu + split + fused dt -------------
__global__ void conv_kernel(const float* __restrict__ conv_w,
                            const float* __restrict__ conv_b,
                            const float* __restrict__ dt_bias,
                            const float* __restrict__ A_log)
{
    const int idx = blockIdx.x * blockDim.x + threadIdx.x; // [0, 1024*2048)
    const int c   = idx & 2047;
    const int grp = idx >> 11;          // 0..1023
    const int b   = grp >> 8;
    const int t0  = (grp & 255) * 8;
    const int row0 = b * LL + t0;

    const float4 wv = *(const float4*)(conv_w + c * 4);
    const float bias = conv_b[c];

    float v[11];
#pragma unroll
    for (int j = 0; j < 11; j++) {
        const int t = t0 + j - 3;
        v[j] = (t >= 0) ? g_zx[(size_t)(b * LL + t) * 3088 + 1024 + c] : 0.f;
    }

#pragma unroll
    for (int j = 0; j < 8; j++) {
        float acc = bias;
        acc = fmaf(v[j],     wv.x, acc);
        acc = fmaf(v[j + 1], wv.y, acc);
        acc = fmaf(v[j + 2], wv.z, acc);
        acc = fmaf(v[j + 3], wv.w, acc);
        const float val = acc / (1.f + __expf(-acc));
        const int row = row0 + j;
        if (c < 1024)       g_X[(size_t)row * 1024 + c] = val;
        else if (c < 1536) {
            const int i = c - 1024;
            g_BmT[(size_t)row * 512 + (i & 3) * 128 + (i >> 2)] = val;
        } else {
            const int i = c - 1536;
            g_CmT[(size_t)row * 512 + (i & 3) * 128 + (i >> 2)] = val;
        }
    }

    if (c < 16) {
        const float ex = __expf(A_log[c]);
        const float db = dt_bias[c];
#pragma unroll
        for (int j = 0; j < 8; j++) {
            const int row = row0 + j;
            const float x = g_zx[(size_t)row * 3088 + 3072 + c] + db;
            const float dt = (x > 20.f) ? x : log1pf(__expf(x));
            const size_t o = ((size_t)b * 16 + c) * LL + (t0 + j);
            g_dth[o] = dt;
            g_La [o] = -ex * dt;
        }
    }
}

// ---------------- chunk-local inclusive cumsum of logdec --------------------------
__global__ void __launch_bounds__(256) cumsum_kernel()
{
    const int gw   = blockIdx.x * 8 + (threadIdx.x >> 5);
    const int lane = threadIdx.x & 31;
    const int c    = gw & (NCHUNK - 1);
    const int bh   = gw >> 5;
    float* base = g_La + (size_t)bh * LL + c * QC;
    float v0 = base[2 * lane];
    float v1 = base[2 * lane + 1];
    float s  = v0 + v1;
#pragma unroll
    for (int o = 1; o < 32; o <<= 1) {
        float other = __shfl_up_sync(0xffffffffu, s, o);
        if (lane >= o) s += other;
    }
    const float excl = s - (v0 + v1);
    base[2 * lane]     = excl + v0;
    base[2 * lane + 1] = excl + v0 + v1;
}

// ---------------- K_P: per-chunk state contribution -------------------------------
__global__ void __launch_bounds__(256) pstate_kernel()
{
    const int bx = blockIdx.x;
    const int hh = bx & 15;
    const int cc = (bx >> 4) & (NCHUNK - 1);
    const int bb = bx >> 9;
    const int tid = threadIdx.x;

    __shared__ __align__(16) float sX[256][16];
    __shared__ float sW[64];

    const int brow = bb * LL + cc * QC;
    {
        const int s = tid >> 2, q = tid & 3;
        const float4* src = (const float4*)(g_X + (size_t)(brow + s) * 1024 + hh * 64 + q * 16);
        float4* dst = (float4*)&sX[(s << 2) | q][0];
#pragma unroll
        for (int i = 0; i < 4; i++) dst[i] = src[i];
    }
    if (tid < 64) {
        const float* Lab = g_La  + ((size_t)bb * 16 + hh) * LL + cc * QC;
        const float* Dtb = g_dth + ((size_t)bb * 16 + hh) * LL + cc * QC;
        sW[tid] = __expf(Lab[63] - Lab[tid]) * Dtb[tid];
    }
    __syncthreads();

    const int n  = tid & 127;
    const int ph = tid >> 7;
    float a[8];
#pragma unroll
    for (int i = 0; i < 8; i++) a[i] = 0.f;

    const float* Bb = g_BmT + (size_t)brow * 512 + n;
    for (int s = 0; s < QC; s++) {
        const float w = sW[s];
#pragma unroll
        for (int rp = 0; rp < 4; rp++) {
            const float bw = __ldg(Bb + (size_t)s * 512 + rp * 128) * w;
            const float4 x0 = *(const float4*)&sX[s * 4 + rp][ph * 8];
            const float4 x1 = *(const float4*)&sX[s * 4 + rp][ph * 8 + 4];
            a[0] = fmaf(bw, x0.x, a[0]); a[1] = fmaf(bw, x0.y, a[1]);
            a[2] = fmaf(bw, x0.z, a[2]); a[3] = fmaf(bw, x0.w, a[3]);
            a[4] = fmaf(bw, x1.x, a[4]); a[5] = fmaf(bw, x1.y, a[5]);
            a[6] = fmaf(bw, x1.z, a[6]); a[7] = fmaf(bw, x1.w, a[7]);
        }
    }
    float* Pp = g_P + (size_t)bx * 2048 + n * 16 + ph * 8;
    *(float4*)Pp       = make_float4(a[0], a[1], a[2], a[3]);
    *(float4*)(Pp + 4) = make_float4(a[4], a[5], a[6], a[7]);
}

// ---------------- K_carry: sequential chunk-state chain ---------------------------
__global__ void __launch_bounds__(256) carry_kernel()
{
    const int bx = blockIdx.x;
    const int bb = bx >> 4;
    const int hh = bx & 15;
    const int off = threadIdx.x * 8;
    const float* Lab = g_La + ((size_t)bb * 16 + hh) * LL;

    float4 s0 = make_float4(0.f,0.f,0.f,0.f);
    float4 s1 = make_float4(0.f,0.f,0.f,0.f);
    for (int c = 0; c < NCHUNK; c++) {
        const size_t slot = ((size_t)(bb * NCHUNK + c) * 16 + hh) * 2048 + off;
        *(float4*)(g_S + slot)     = s0;
        *(float4*)(g_S + slot + 4) = s1;
        const float ef = __expf(Lab[c * QC + 63]);
        const float4 p0 = *(const float4*)(g_P + slot);
        const float4 p1 = *(const float4*)(g_P + slot + 4);
        s0.x = fmaf(ef, s0.x, p0.x); s0.y = fmaf(ef, s0.y, p0.y);
        s0.z = fmaf(ef, s0.z, p0.z); s0.w = fmaf(ef, s0.w, p0.w);
        s1.x = fmaf(ef, s1.x, p1.x); s1.y = fmaf(ef, s1.y, p1.y);
        s1.z = fmaf(ef, s1.z, p1.z); s1.w = fmaf(ef, s1.w, p1.w);
    }
}

// ---------------- K_y: y = inter + intra, fused D_skip + z-gate -------------------
__global__ void __launch_bounds__(256) yout_kernel(const float* __restrict__ D_skip)
{
    const int bx = blockIdx.x;
    const int hh = bx & 15;
    const int cc = (bx >> 4) & (NCHUNK - 1);
    const int bb = bx >> 9;
    const int tid = threadIdx.x;
    const int t = tid >> 2;
    const int r = tid & 3;

    __shared__ __align__(16) float sX[256][16];
    __shared__ __align__(16) float sS[128][16];
    __shared__ float sLa[64], sDt[64];

    const int brow = bb * LL + cc * QC;
    {
        const int s = tid >> 2, q = tid & 3;
        const float4* src = (const float4*)(g_X + (size_t)(brow + s) * 1024 + hh * 64 + q * 16);
        float4* dst = (float4*)&sX[(s << 2) | q][0];
#pragma unroll
        for (int i = 0; i < 4; i++) dst[i] = src[i];
    }
    {
        const float4* src = (const float4*)(g_S + (size_t)bx * 2048 + tid * 8);
        float4* dst = (float4*)(&sS[0][0] + tid * 8);
        dst[0] = src[0]; dst[1] = src[1];
    }
    if (tid < 64) {
        sLa[tid] = g_La [((size_t)bb * 16 + hh) * LL + cc * QC + tid];
        sDt[tid] = g_dth[((size_t)bb * 16 + hh) * LL + cc * QC + tid];
    }
    __syncthreads();

    float acc[16];
#pragma unroll
    for (int i = 0; i < 16; i++) acc[i] = 0.f;

    const float4* crow = (const float4*)(g_CmT + (size_t)(brow + t) * 512 + r * 128);
    for (int nq = 0; nq < 32; nq++) {
        const float4 cv = __ldg(crow + nq);
#pragma unroll
        for (int j = 0; j < 4; j++) {
            const float cn = (j == 0) ? cv.x : (j == 1) ? cv.y : (j == 2) ? cv.z : cv.w;
            const float* sr = &sS[nq * 4 + j][0];
#pragma unroll
            for (int p = 0; p < 16; p++) acc[p] = fmaf(cn, sr[p], acc[p]);
        }
    }
    const float lat = sLa[t];
    const float einter = __expf(lat);
#pragma unroll
    for (int p = 0; p < 16; p++) acc[p] *= einter;

    const float4* Gp = (const float4*)(g_G + (size_t)(bb * NCHUNK + cc) * 65536 + (size_t)tid * 256);
    for (int s = 0; s <= t; s++) {
        const float w = __expf(lat - sLa[s]) * sDt[s];
        const float4 gv = __ldg(Gp + s);
        const float g0 = gv.x * w, g1 = gv.y * w, g2 = gv.z * w, g3 = gv.w * w;
        const float* x0 = &sX[s * 4 + 0][0];
        const float* x1 = &sX[s * 4 + 1][0];
        const float* x2 = &sX[s * 4 + 2][0];
        const float* x3 = &sX[s * 4 + 3][0];
#pragma unroll
        for (int p = 0; p < 16; p++) {
            float v = fmaf(g0, x0[p], acc[p]);
            v = fmaf(g1, x1[p], v);
            v = fmaf(g2, x2[p], v);
            acc[p] = fmaf(g3, x3[p], v);
        }
    }

    const float dsk = D_skip[hh];
    const int row = brow + t;
    const float* xv = &sX[tid][0];
    float* go = g_g + (size_t)row * 1024 + hh * 64 + r * 16;
    const float* zp = g_zx + (size_t)row * 3088 + hh * 64 + r * 16;
#pragma unroll
    for (int p = 0; p < 16; p++) {
        const float y = fmaf(xv[p], dsk, acc[p]);
        const float z = zp[p];
        go[p] = y * (z / (1.f + __expf(-z)));
    }
}

// ---------------- RMSNorm ---------------------------------------------------------
__global__ void __launch_bounds__(256) rms_kernel(float* __restrict__ out)
{
    const int warp = threadIdx.x >> 5;
    const int lane = threadIdx.x & 31;
    const int row  = blockIdx.x * 8 + warp;
    const float* r = g_res + (size_t)row * 512;
    float v[16];
    float ss = 0.f;
#pragma unroll
    for (int i = 0; i < 16; i++) { v[i] = r[lane + i * 32]; ss = fmaf(v[i], v[i], ss); }
#pragma unroll
    for (int o = 16; o >= 1; o >>= 1) ss += __shfl_xor_sync(0xffffffffu, ss, o);
    const float sc = rsqrtf(ss * (1.f / 512.f) + 1e-5f);
    float* o = out + (size_t)row * 512;
#pragma unroll
    for (int i = 0; i < 16; i++) o[lane + i * 32] = v[i] * sc;
}

// ---------------- launch ----------------------------------------------------------
extern "C" void kernel_launch(void* const* d_in, const int* in_sizes, int n_in,
                              void* d_out, int out_size)
{
    const float* hs      = (const float*)d_in[0];
    const float* W_in    = (const float*)d_in[1];
    const float* conv_w  = (const float*)d_in[2];
    const float* conv_b  = (const float*)d_in[3];
    const float* dt_bias = (const float*)d_in[4];
    const float* A_log   = (const float*)d_in[5];
    const float* D_skip  = (const float*)d_in[6];
    const float* W_out   = (const float*)d_in[7];
    float* out = (float*)d_out;

    gemm1_kernel<<<dim3(25, 64), 256>>>(hs, W_in);
    conv_kernel<<<NROWS / 8 * 2048 / 256, 256>>>(conv_w, conv_b, dt_bias, A_log);
    cumsum_kernel<<<256, 256>>>();
    pstate_kernel<<<2048, 256>>>();      // launch #4 -> ncu capture slot
    gscore_kernel<<<dim3(2, 2, 128), 256>>>();
    carry_kernel<<<64, 256>>>();
    yout_kernel<<<2048, 256>>>(D_skip);
    gemm2_kernel<<<dim3(4, 64), 256>>>(W_out, hs);
    rms_kernel<<<NROWS / 8, 256>>>(out);
}

// round 17
// speedup vs baseline: 1.0657x; 1.0021x over previous
#include <cuda_runtime.h>
#include <math.h>
#include <stdint.h>

#define LL 2048
#define NROWS 8192   // B*L
#define QC 64        // chunk length
#define NCHUNK 32    // chunks per batch

// ---------------- scratch (device globals; no runtime allocation) ----------------
static __device__ float g_zx [NROWS * 3088]; // zxbcdt
static __device__ float g_X  [NROWS * 1024]; // silu(conv) x part [row][h*64+r*16+p]
static __device__ float g_Bm [NROWS * 512];  // B  [row][n*4+r]   (pstate, vectorized)
static __device__ float g_BmT[NROWS * 512];  // B^T [row][r*128+n] (gscore)
static __device__ float g_CmT[NROWS * 512];  // C^T [row][r*128+n]
static __device__ float g_dth[4 * 16 * LL];  // dt  [b,h,t]
static __device__ float g_La [4 * 16 * LL];  // chunk-local cumsum(logdec) [b,h,t]
static __device__ float g_G  [128 * 65536];  // scores [b*32+c][tq*256+sq]
static __device__ float g_P  [2048 * 2048];  // chunk state contrib
static __device__ float g_S  [2048 * 2048];  // chunk-start states
static __device__ float g_g  [NROWS * 1024]; // gated
static __device__ float g_res[NROWS * 512];  // pre-norm residual

// ---------------- tf32 helpers (gscore) --------------------------------------------
__device__ __forceinline__ uint32_t f2tf32(float v) {
    uint32_t r;
    asm("cvt.rna.tf32.f32 %0, %1;" : "=r"(r) : "f"(v));
    return r;
}
__device__ __forceinline__ void split_tf32(float v, float& hi, float& lo) {
    uint32_t h = f2tf32(v);
    hi = __uint_as_float(h);
    float l = v - hi;
    lo = __uint_as_float(f2tf32(l));
}
__device__ __forceinline__ void mma_tf32(float d[4],
                                         uint32_t a0, uint32_t a1, uint32_t a2, uint32_t a3,
                                         uint32_t b0, uint32_t b1) {
    asm volatile(
        "mma.sync.aligned.m16n8k8.row.col.f32.tf32.tf32.f32 "
        "{%0,%1,%2,%3}, {%4,%5,%6,%7}, {%8,%9}, {%0,%1,%2,%3};"
        : "+f"(d[0]), "+f"(d[1]), "+f"(d[2]), "+f"(d[3])
        : "r"(a0), "r"(a1), "r"(a2), "r"(a3), "r"(b0), "r"(b1));
}

// ---------------- bf16 helpers ------------------------------------------------------
__device__ __forceinline__ void bsplit2(float x0, float x1, uint32_t& hi, uint32_t& lo) {
    asm("cvt.rn.bf16x2.f32 %0, %2, %1;" : "=r"(hi) : "f"(x0), "f"(x1));
    const float h0 = __uint_as_float(hi << 16);
    const float h1 = __uint_as_float(hi & 0xffff0000u);
    const float l0 = x0 - h0;
    const float l1 = x1 - h1;
    asm("cvt.rn.bf16x2.f32 %0, %2, %1;" : "=r"(lo) : "f"(l0), "f"(l1));
}
__device__ __forceinline__ void mma_bf16(float d[4],
                                         uint32_t a0, uint32_t a1, uint32_t a2, uint32_t a3,
                                         uint32_t b0, uint32_t b1) {
    asm volatile(
        "mma.sync.aligned.m16n8k16.row.col.f32.bf16.bf16.f32 "
        "{%0,%1,%2,%3}, {%4,%5,%6,%7}, {%8,%9}, {%0,%1,%2,%3};"
        : "+f"(d[0]), "+f"(d[1]), "+f"(d[2]), "+f"(d[3])
        : "r"(a0), "r"(a1), "r"(a2), "r"(a3), "r"(b0), "r"(b1));
}
__device__ __forceinline__ void ldsm_x4(uint32_t& r0, uint32_t& r1, uint32_t& r2, uint32_t& r3,
                                        uint32_t addr) {
    asm volatile("ldmatrix.sync.aligned.m8n8.x4.shared.b16 {%0,%1,%2,%3}, [%4];"
                 : "=r"(r0), "=r"(r1), "=r"(r2), "=r"(r3) : "r"(addr));
}
__device__ __forceinline__ void ldsm_x2_t(uint32_t& r0, uint32_t& r1, uint32_t addr) {
    asm volatile("ldmatrix.sync.aligned.m8n8.x2.trans.shared.b16 {%0,%1}, [%2];"
                 : "=r"(r0), "=r"(r1) : "r"(addr));
}

// ---------------- BF16 3-pass GEMM with ldmatrix fragment loads --------------------
template<int Nv, int Kv, bool GUARD, bool ADDRES>
__device__ __forceinline__ void gemm_bf16_body(const float* __restrict__ A,
                                               const float* __restrict__ Bw,
                                               float* __restrict__ C,
                                               const float* __restrict__ Res,
                                               int mbase, int nbase)
{
    __shared__ __align__(16) uint32_t sA[2][2][128 * 12];
    __shared__ __align__(16) uint32_t sB[2][2][16 * 68];

    const int tid   = threadIdx.x;
    const int warp  = tid >> 5;
    const int lane  = tid & 31;
    const int warpM = warp & 1;
    const int warpN = warp >> 1;

    const int aRow  = tid >> 1;
    const int aHalf = tid & 1;
    const int bK2   = tid >> 5;
    const int bCol  = (tid & 31) * 4;

    const float* Ap  = A + (size_t)(mbase + aRow) * Kv + aHalf * 8;
    const float* Bp0 = Bw + (size_t)(2 * bK2) * Nv + nbase + bCol;
    const float* Bp1 = Bp0 + Nv;
    const bool  bOK = (!GUARD) || (nbase + bCol + 3 < Nv);

    const int aLRow = (lane & 7) + ((lane >> 3) & 1) * 8;
    const int aLK   = (lane >> 4) * 16;
    const int bLRow = (lane & 7) + ((lane >> 3) & 1) * 8;

    uint32_t aBase[2][2], bBase[2][2];
#pragma unroll
    for (int bu = 0; bu < 2; bu++)
#pragma unroll
        for (int hf = 0; hf < 2; hf++) {
            aBase[bu][hf] = (uint32_t)__cvta_generic_to_shared(&sA[bu][hf][0]);
            bBase[bu][hf] = (uint32_t)__cvta_generic_to_shared(&sB[bu][hf][0]);
        }

    float acc[4][4][4];
#pragma unroll
    for (int mt = 0; mt < 4; mt++)
#pragma unroll
        for (int nt = 0; nt < 4; nt++)
#pragma unroll
            for (int i = 0; i < 4; i++) acc[mt][nt][i] = 0.f;

#define STORE_A(bu, av0, av1) do { \
        uint32_t h0,l0,h1,l1,h2,l2,h3,l3; \
        bsplit2((av0).x,(av0).y,h0,l0); bsplit2((av0).z,(av0).w,h1,l1); \
        bsplit2((av1).x,(av1).y,h2,l2); bsplit2((av1).z,(av1).w,h3,l3); \
        const uint32_t off = aRow * 12 + aHalf * 4; \
        *(uint4*)&sA[bu][0][off] = make_uint4(h0,h1,h2,h3); \
        *(uint4*)&sA[bu][1][off] = make_uint4(l0,l1,l2,l3); \
    } while (0)
#define STORE_B(bu, bv0, bv1) do { \
        uint32_t h0,l0,h1,l1,h2,l2,h3,l3; \
        bsplit2((bv0).x,(bv0).y,h0,l0); bsplit2((bv0).z,(bv0).w,h1,l1); \
        bsplit2((bv1).x,(bv1).y,h2,l2); bsplit2((bv1).z,(bv1).w,h3,l3); \
        const uint32_t off0 = (2 * bK2) * 68 + (bCol >> 1); \
        *(uint2*)&sB[bu][0][off0]      = make_uint2(h0,h1); \
        *(uint2*)&sB[bu][1][off0]      = make_uint2(l0,l1); \
        *(uint2*)&sB[bu][0][off0 + 68] = make_uint2(h2,h3); \
        *(uint2*)&sB[bu][1][off0 + 68] = make_uint2(l2,l3); \
    } while (0)

    {
        float4 av0 = *(const float4*)Ap;
        float4 av1 = *(const float4*)(Ap + 4);
        float4 bv0 = bOK ? *(const float4*)Bp0 : make_float4(0.f,0.f,0.f,0.f);
        float4 bv1 = bOK ? *(const float4*)Bp1 : make_float4(0.f,0.f,0.f,0.f);
        STORE_A(0, av0, av1);
        STORE_B(0, bv0, bv1);
    }
    __syncthreads();

    const int NK = Kv / 16;
    for (int ks = 0; ks < NK; ks++) {
        const int buf = ks & 1;
        float4 av0, av1, bv0, bv1;
        const bool hasNext = (ks + 1 < NK);
        if (hasNext) {
            av0 = *(const float4*)(Ap + (ks + 1) * 16);
            av1 = *(const float4*)(Ap + (ks + 1) * 16 + 4);
            bv0 = bOK ? *(const float4*)(Bp0 + (size_t)(ks + 1) * 16 * Nv)
                      : make_float4(0.f,0.f,0.f,0.f);
            bv1 = bOK ? *(const float4*)(Bp1 + (size_t)(ks + 1) * 16 * Nv)
                      : make_float4(0.f,0.f,0.f,0.f);
        }

        uint32_t ah[4][4], al[4][4], bh[4][2], bl[4][2];
#pragma unroll
        for (int mt = 0; mt < 4; mt++) {
            const uint32_t rb = (warpM * 64 + mt * 16 + aLRow) * 48 + aLK;
            ldsm_x4(ah[mt][0], ah[mt][1], ah[mt][2], ah[mt][3], aBase[buf][0] + rb);
            ldsm_x4(al[mt][0], al[mt][1], al[mt][2], al[mt][3], aBase[buf][1] + rb);
        }
#pragma unroll
        for (int nt = 0; nt < 4; nt++) {
            const uint32_t rb = bLRow * 272 + (warpN * 32 + nt * 8) * 2;
            ldsm_x2_t(bh[nt][0], bh[nt][1], bBase[buf][0] + rb);
            ldsm_x2_t(bl[nt][0], bl[nt][1], bBase[buf][1] + rb);
        }

#pragma unroll
        for (int mt = 0; mt < 4; mt++)
#pragma unroll
            for (int nt = 0; nt < 4; nt++) {
                mma_bf16(acc[mt][nt], ah[mt][0], ah[mt][1], ah[mt][2], ah[mt][3],
                         bh[nt][0], bh[nt][1]);
                mma_bf16(acc[mt][nt], ah[mt][0], ah[mt][1], ah[mt][2], ah[mt][3],
                         bl[nt][0], bl[nt][1]);
                mma_bf16(acc[mt][nt], al[mt][0], al[mt][1], al[mt][2], al[mt][3],
                         bh[nt][0], bh[nt][1]);
            }

        if (hasNext) {
            const int nb = buf ^ 1;
            STORE_A(nb, av0, av1);
            STORE_B(nb, bv0, bv1);
        }
        __syncthreads();
    }
#undef STORE_A
#undef STORE_B

    const int gid = lane >> 2;
    const int tig = lane & 3;
#pragma unroll
    for (int mt = 0; mt < 4; mt++) {
        const int row0 = mbase + warpM * 64 + mt * 16 + gid;
#pragma unroll
        for (int nt = 0; nt < 4; nt++) {
            const int col = nbase + warpN * 32 + nt * 8 + tig * 2;
            if (!GUARD || col < Nv) {
                float2 v0 = make_float2(acc[mt][nt][0], acc[mt][nt][1]);
                float2 v1 = make_float2(acc[mt][nt][2], acc[mt][nt][3]);
                if (ADDRES) {
                    float2 r0 = *(const float2*)(Res + (size_t)row0 * Nv + col);
                    float2 r1 = *(const float2*)(Res + (size_t)(row0 + 8) * Nv + col);
                    v0.x += r0.x; v0.y += r0.y; v1.x += r1.x; v1.y += r1.y;
                }
                *(float2*)(C + (size_t)row0 * Nv + col)       = v0;
                *(float2*)(C + (size_t)(row0 + 8) * Nv + col) = v1;
            }
        }
    }
}

__global__ void __launch_bounds__(256) gemm1_kernel(const float* __restrict__ A,
                                                    const float* __restrict__ W)
{
    gemm_bf16_body<3088, 512, true, false>(A, W, g_zx, nullptr,
                                           blockIdx.y * 128, blockIdx.x * 128);
}

__global__ void __launch_bounds__(256) gemm2_kernel(const float* __restrict__ W,
                                                    const float* __restrict__ Res)
{
    gemm_bf16_body<512, 1024, false, true>(g_g, W, g_res, Res,
                                           blockIdx.y * 128, blockIdx.x * 128);
}

// ---------------- K_G: G = Chat @ Bhat^T per (b,chunk), TF32 3-pass ---------------
__global__ void __launch_bounds__(256) gscore_kernel()
{
    __shared__ __align__(16) float sA[2][2][8][136];
    __shared__ __align__(16) float sB[2][2][8][136];

    const int tid   = threadIdx.x;
    const int warp  = tid >> 5;
    const int lane  = tid & 31;
    const int gid   = lane >> 2;
    const int tig   = lane & 3;
    const int warpM = warp & 1;
    const int warpN = warp >> 1;
    const int ldRow = tid >> 1;
    const int ldCol = (tid & 1) * 4;

    const int bc    = blockIdx.z;
    const int nbase = blockIdx.x * 128;
    const int mbase = blockIdx.y * 128;
    const float* Ap = g_CmT + (size_t)bc * 32768 + (size_t)(mbase + ldRow) * 128 + ldCol;
    const float* Bp = g_BmT + (size_t)bc * 32768 + (size_t)(nbase + ldRow) * 128 + ldCol;
    float* Cp = g_G + (size_t)bc * 65536;

    float acc[4][4][4];
#pragma unroll
    for (int mt = 0; mt < 4; mt++)
#pragma unroll
        for (int nt = 0; nt < 4; nt++)
#pragma unroll
            for (int i = 0; i < 4; i++) acc[mt][nt][i] = 0.f;

    {
        float4 av = *(const float4*)Ap;
        float4 bv = *(const float4*)Bp;
        float h, l;
        split_tf32(av.x, h, l); sA[0][0][ldCol+0][ldRow] = h; sA[0][1][ldCol+0][ldRow] = l;
        split_tf32(av.y, h, l); sA[0][0][ldCol+1][ldRow] = h; sA[0][1][ldCol+1][ldRow] = l;
        split_tf32(av.z, h, l); sA[0][0][ldCol+2][ldRow] = h; sA[0][1][ldCol+2][ldRow] = l;
        split_tf32(av.w, h, l); sA[0][0][ldCol+3][ldRow] = h; sA[0][1][ldCol+3][ldRow] = l;
        split_tf32(bv.x, h, l); sB[0][0][ldCol+0][ldRow] = h; sB[0][1][ldCol+0][ldRow] = l;
        split_tf32(bv.y, h, l); sB[0][0][ldCol+1][ldRow] = h; sB[0][1][ldCol+1][ldRow] = l;
        split_tf32(bv.z, h, l); sB[0][0][ldCol+2][ldRow] = h; sB[0][1][ldCol+2][ldRow] = l;
        split_tf32(bv.w, h, l); sB[0][0][ldCol+3][ldRow] = h; sB[0][1][ldCol+3][ldRow] = l;
    }
    __syncthreads();

    for (int ks = 0; ks < 16; ks++) {
        const int buf = ks & 1;
        float4 av, bv;
        const bool hasNext = (ks + 1 < 16);
        if (hasNext) {
            av = *(const float4*)(Ap + (ks + 1) * 8);
            bv = *(const float4*)(Bp + (ks + 1) * 8);
        }

        const float (*Ah)[136] = sA[buf][0];
        const float (*Al)[136] = sA[buf][1];
        const float (*Bh)[136] = sB[buf][0];
        const float (*Bl)[136] = sB[buf][1];

        uint32_t ah[4][4], al[4][4], bh[4][2], bl[4][2];
#pragma unroll
        for (int mt = 0; mt < 4; mt++) {
            const int r = warpM * 64 + mt * 16 + gid;
            ah[mt][0] = __float_as_uint(Ah[tig    ][r    ]);
            ah[mt][1] = __float_as_uint(Ah[tig    ][r + 8]);
            ah[mt][2] = __float_as_uint(Ah[tig + 4][r    ]);
            ah[mt][3] = __float_as_uint(Ah[tig + 4][r + 8]);
            al[mt][0] = __float_as_uint(Al[tig    ][r    ]);
            al[mt][1] = __float_as_uint(Al[tig    ][r + 8]);
            al[mt][2] = __float_as_uint(Al[tig + 4][r    ]);
            al[mt][3] = __float_as_uint(Al[tig + 4][r + 8]);
        }
#pragma unroll
        for (int nt = 0; nt < 4; nt++) {
            const int c = warpN * 32 + nt * 8 + gid;
            bh[nt][0] = __float_as_uint(Bh[tig    ][c]);
            bh[nt][1] = __float_as_uint(Bh[tig + 4][c]);
            bl[nt][0] = __float_as_uint(Bl[tig    ][c]);
            bl[nt][1] = __float_as_uint(Bl[tig + 4][c]);
        }

#pragma unroll
        for (int mt = 0; mt < 4; mt++)
#pragma unroll
            for (int nt = 0; nt < 4; nt++) {
                mma_tf32(acc[mt][nt], ah[mt][0], ah[mt][1], ah[mt][2], ah[mt][3],
                         bh[nt][0], bh[nt][1]);
                mma_tf32(acc[mt][nt], ah[mt][0], ah[mt][1], ah[mt][2], ah[mt][3],
                         bl[nt][0], bl[nt][1]);
                mma_tf32(acc[mt][nt], al[mt][0], al[mt][1], al[mt][2], al[mt][3],
                         bh[nt][0], bh[nt][1]);
            }

        if (hasNext) {
            const int nb = buf ^ 1;
            float h, l;
            split_tf32(av.x, h, l); sA[nb][0][ldCol+0][ldRow] = h; sA[nb][1][ldCol+0][ldRow] = l;
            split_tf32(av.y, h, l); sA[nb][0][ldCol+1][ldRow] = h; sA[nb][1][ldCol+1][ldRow] = l;
            split_tf32(av.z, h, l); sA[nb][0][ldCol+2][ldRow] = h; sA[nb][1][ldCol+2][ldRow] = l;
            split_tf32(av.w, h, l); sA[nb][0][ldCol+3][ldRow] = h; sA[nb][1][ldCol+3][ldRow] = l;
            split_tf32(bv.x, h, l); sB[nb][0][ldCol+0][ldRow] = h; sB[nb][1][ldCol+0][ldRow] = l;
            split_tf32(bv.y, h, l); sB[nb][0][ldCol+1][ldRow] = h; sB[nb][1][ldCol+1][ldRow] = l;
            split_tf32(bv.z, h, l); sB[nb][0][ldCol+2][ldRow] = h; sB[nb][1][ldCol+2][ldRow] = l;
            split_tf32(bv.w, h, l); sB[nb][0][ldCol+3][ldRow] = h; sB[nb][1][ldCol+3][ldRow] = l;
        }
        __syncthreads();
    }

#pragma unroll
    for (int mt = 0; mt < 4; mt++) {
        const int row0 = mbase + warpM * 64 + mt * 16 + gid;
#pragma unroll
        for (int nt = 0; nt < 4; nt++) {
            const int col = nbase + warpN * 32 + nt * 8 + tig * 2;
            *(float2*)(Cp + (size_t)row0 * 256 + col)       = make_float2(acc[mt][nt][0], acc[mt][nt][1]);
            *(float2*)(Cp + (size_t)(row0 + 8) * 256 + col) = make_float2(acc[mt][nt][2], acc[mt][nt][3]);
        }
    }
}

// ---------------- conv1d tiled (8 t/thread) + silu + split + fused dt -------------
__global__ void conv_kernel(const float* __restrict__ conv_w,
                            const float* __restrict__ conv_b,
                            const float* __restrict__ dt_bias,
                            const float* __restrict__ A_log)
{
    const int idx = blockIdx.x * blockDim.x + threadIdx.x;
    const int c   = idx & 2047;
    const int grp = idx >> 11;
    const int b   = grp >> 8;
    const int t0  = (grp & 255) * 8;
    const int row0 = b * LL + t0;

    const float4 wv = *(const float4*)(conv_w + c * 4);
    const float bias = conv_b[c];

    float v[11];
#pragma unroll
    for (int j = 0; j < 11; j++) {
        const int t = t0 + j - 3;
        v[j] = (t >= 0) ? g_zx[(size_t)(b * LL + t) * 3088 + 1024 + c] : 0.f;
    }

#pragma unroll
    for (int j = 0; j < 8; j++) {
        float acc = bias;
        acc = fmaf(v[j],     wv.x, acc);
        acc = fmaf(v[j + 1], wv.y, acc);
        acc = fmaf(v[j + 2], wv.z, acc);
        acc = fmaf(v[j + 3], wv.w, acc);
        const float val = acc / (1.f + __expf(-acc));
        const int row = row0 + j;
        if (c < 1024)       g_X[(size_t)row * 1024 + c] = val;
        else if (c < 1536) {
            const int i = c - 1024;   // n*4 + r
            g_Bm [(size_t)row * 512 + i] = val;
            g_BmT[(size_t)row * 512 + (i & 3) * 128 + (i >> 2)] = val;
        } else {
            const int i = c - 1536;
            g_CmT[(size_t)row * 512 + (i & 3) * 128 + (i >> 2)] = val;
        }
    }

    if (c < 16) {
        const float ex = __expf(A_log[c]);
        const float db = dt_bias[c];
#pragma unroll
        for (int j = 0; j < 8; j++) {
            const int row = row0 + j;
            const float x = g_zx[(size_t)row * 3088 + 3072 + c] + db;
            const float dt = (x > 20.f) ? x : log1pf(__expf(x));
            const size_t o = ((size_t)b * 16 + c) * LL + (t0 + j);
            g_dth[o] = dt;
            g_La [o] = -ex * dt;
        }
    }
}

// ---------------- chunk-local inclusive cumsum of logdec --------------------------
__global__ void __launch_bounds__(256) cumsum_kernel()
{
    const int gw   = blockIdx.x * 8 + (threadIdx.x >> 5);
    const int lane = threadIdx.x & 31;
    const int c    = gw & (NCHUNK - 1);
    const int bh   = gw >> 5;
    float* base = g_La + (size_t)bh * LL + c * QC;
    float v0 = base[2 * lane];
    float v1 = base[2 * lane + 1];
    float s  = v0 + v1;
#pragma unroll
    for (int o = 1; o < 32; o <<= 1) {
        float other = __shfl_up_sync(0xffffffffu, s, o);
        if (lane >= o) s += other;
    }
    const float excl = s - (v0 + v1);
    base[2 * lane]     = excl + v0;
    base[2 * lane + 1] = excl + v0 + v1;
}

// ---------------- K_P: per-chunk state contribution (vectorized B loads) ----------
__global__ void __launch_bounds__(256) pstate_kernel()
{
    const int bx = blockIdx.x;
    const int hh = bx & 15;
    const int cc = (bx >> 4) & (NCHUNK - 1);
    const int bb = bx >> 9;
    const int tid = threadIdx.x;

    __shared__ __align__(16) float sX[256][16];
    __shared__ float sW[64];

    const int brow = bb * LL + cc * QC;
    {
        const int s = tid >> 2, q = tid & 3;
        const float4* src = (const float4*)(g_X + (size_t)(brow + s) * 1024 + hh * 64 + q * 16);
        float4* dst = (float4*)&sX[(s << 2) | q][0];
#pragma unroll
        for (int i = 0; i < 4; i++) dst[i] = src[i];
    }
    if (tid < 64) {
        const float* Lab = g_La  + ((size_t)bb * 16 + hh) * LL + cc * QC;
        const float* Dtb = g_dth + ((size_t)bb * 16 + hh) * LL + cc * QC;
        sW[tid] = __expf(Lab[63] - Lab[tid]) * Dtb[tid];
    }
    __syncthreads();

    const int n  = tid & 127;
    const int ph = tid >> 7;
    float a[8];
#pragma unroll
    for (int i = 0; i < 8; i++) a[i] = 0.f;

    // one coalesced float4 per step: B[row][n*4 .. n*4+3] = 4 r-values
    const float4* Bb = (const float4*)(g_Bm + (size_t)brow * 512) + n;
    for (int s = 0; s < QC; s++) {
        const float w = sW[s];
        const float4 bv = __ldg(Bb + (size_t)s * 128);
        const float bw0 = bv.x * w, bw1 = bv.y * w, bw2 = bv.z * w, bw3 = bv.w * w;
        const float* xs0 = &sX[s * 4 + 0][ph * 8];
        const float* xs1 = &sX[s * 4 + 1][ph * 8];
        const float* xs2 = &sX[s * 4 + 2][ph * 8];
        const float* xs3 = &sX[s * 4 + 3][ph * 8];
#pragma unroll
        for (int i = 0; i < 8; i++) {
            float t = fmaf(bw0, xs0[i], a[i]);
            t = fmaf(bw1, xs1[i], t);
            t = fmaf(bw2, xs2[i], t);
            a[i] = fmaf(bw3, xs3[i], t);
        }
    }
    float* Pp = g_P + (size_t)bx * 2048 + n * 16 + ph * 8;
    *(float4*)Pp       = make_float4(a[0], a[1], a[2], a[3]);
    *(float4*)(Pp + 4) = make_float4(a[4], a[5], a[6], a[7]);
}

// ---------------- K_carry: sequential chunk-state chain ---------------------------
__global__ void __launch_bounds__(256) carry_kernel()
{
    const int bx = blockIdx.x;
    const int bb = bx >> 4;
    const int hh = bx & 15;
    const int off = threadIdx.x * 8;
    const float* Lab = g_La + ((size_t)bb * 16 + hh) * LL;

    float4 s0 = make_float4(0.f,0.f,0.f,0.f);
    float4 s1 = make_float4(0.f,0.f,0.f,0.f);
    for (int c = 0; c < NCHUNK; c++) {
        const size_t slot = ((size_t)(bb * NCHUNK + c) * 16 + hh) * 2048 + off;
        *(float4*)(g_S + slot)     = s0;
        *(float4*)(g_S + slot + 4) = s1;
        const float ef = __expf(Lab[c * QC + 63]);
        const float4 p0 = *(const float4*)(g_P + slot);
        const float4 p1 = *(const float4*)(g_P + slot + 4);
        s0.x = fmaf(ef, s0.x, p0.x); s0.y = fmaf(ef, s0.y, p0.y);
        s0.z = fmaf(ef, s0.z, p0.z); s0.w = fmaf(ef, s0.w, p0.w);
        s1.x = fmaf(ef, s1.x, p1.x); s1.y = fmaf(ef, s1.y, p1.y);
        s1.z = fmaf(ef, s1.z, p1.z); s1.w = fmaf(ef, s1.w, p1.w);
    }
}

// ---------------- K_y: y = inter + intra, fused D_skip + z-gate -------------------
__global__ void __launch_bounds__(256) yout_kernel(const float* __restrict__ D_skip)
{
    const int bx = blockIdx.x;
    const int hh = bx & 15;
    const int cc = (bx >> 4) & (NCHUNK - 1);
    const int bb = bx >> 9;
    const int tid = threadIdx.x;
    const int t = tid >> 2;
    const int r = tid & 3;

    __shared__ __align__(16) float sX[256][16];
    __shared__ __align__(16) float sS[128][16];
    __shared__ float sLa[64], sDt[64];

    const int brow = bb * LL + cc * QC;
    {
        const int s = tid >> 2, q = tid & 3;
        const float4* src = (const float4*)(g_X + (size_t)(brow + s) * 1024 + hh * 64 + q * 16);
        float4* dst = (float4*)&sX[(s << 2) | q][0];
#pragma unroll
        for (int i = 0; i < 4; i++) dst[i] = src[i];
    }
    {
        const float4* src = (const float4*)(g_S + (size_t)bx * 2048 + tid * 8);
        float4* dst = (float4*)(&sS[0][0] + tid * 8);
        dst[0] = src[0]; dst[1] = src[1];
    }
    if (tid < 64) {
        sLa[tid] = g_La [((size_t)bb * 16 + hh) * LL + cc * QC + tid];
        sDt[tid] = g_dth[((size_t)bb * 16 + hh) * LL + cc * QC + tid];
    }
    __syncthreads();

    float acc[16];
#pragma unroll
    for (int i = 0; i < 16; i++) acc[i] = 0.f;

    const float4* crow = (const float4*)(g_CmT + (size_t)(brow + t) * 512 + r * 128);
    for (int nq = 0; nq < 32; nq++) {
        const float4 cv = __ldg(crow + nq);
#pragma unroll
        for (int j = 0; j < 4; j++) {
            const float cn = (j == 0) ? cv.x : (j == 1) ? cv.y : (j == 2) ? cv.z : cv.w;
            const float* sr = &sS[nq * 4 + j][0];
#pragma unroll
            for (int p = 0; p < 16; p++) acc[p] = fmaf(cn, sr[p], acc[p]);
        }
    }
    const float lat = sLa[t];
    const float einter = __expf(lat);
#pragma unroll
    for (int p = 0; p < 16; p++) acc[p] *= einter;

    const float4* Gp = (const float4*)(g_G + (size_t)(bb * NCHUNK + cc) * 65536 + (size_t)tid * 256);
    for (int s = 0; s <= t; s++) {
        const float w = __expf(lat - sLa[s]) * sDt[s];
        const float4 gv = __ldg(Gp + s);
        const float g0 = gv.x * w, g1 = gv.y * w, g2 = gv.z * w, g3 = gv.w * w;
        const float* x0 = &sX[s * 4 + 0][0];
        const float* x1 = &sX[s * 4 + 1][0];
        const float* x2 = &sX[s * 4 + 2][0];
        const float* x3 = &sX[s * 4 + 3][0];
#pragma unroll
        for (int p = 0; p < 16; p++) {
            float v = fmaf(g0, x0[p], acc[p]);
            v = fmaf(g1, x1[p], v);
            v = fmaf(g2, x2[p], v);
            acc[p] = fmaf(g3, x3[p], v);
        }
    }

    const float dsk = D_skip[hh];
    const int row = brow + t;
    const float* xv = &sX[tid][0];
    float* go = g_g + (size_t)row * 1024 + hh * 64 + r * 16;
    const float* zp = g_zx + (size_t)row * 3088 + hh * 64 + r * 16;
#pragma unroll
    for (int p = 0; p < 16; p++) {
        const float y = fmaf(xv[p], dsk, acc[p]);
        const float z = zp[p];
        go[p] = y * (z / (1.f + __expf(-z)));
    }
}

// ---------------- RMSNorm ---------------------------------------------------------
__global__ void __launch_bounds__(256) rms_kernel(float* __restrict__ out)
{
    const int warp = threadIdx.x >> 5;
    const int lane = threadIdx.x & 31;
    const int row  = blockIdx.x * 8 + warp;
    const float* r = g_res + (size_t)row * 512;
    float v[16];
    float ss = 0.f;
#pragma unroll
    for (int i = 0; i < 16; i++) { v[i] = r[lane + i * 32]; ss = fmaf(v[i], v[i], ss); }
#pragma unroll
    for (int o = 16; o >= 1; o >>= 1) ss += __shfl_xor_sync(0xffffffffu, ss, o);
    const float sc = rsqrtf(ss * (1.f / 512.f) + 1e-5f);
    float* o = out + (size_t)row * 512;
#pragma unroll
    for (int i = 0; i < 16; i++) o[lane + i * 32] = v[i] * sc;
}

// ---------------- launch (serial chain — proven capturable) -----------------------
extern "C" void kernel_launch(void* const* d_in, const int* in_sizes, int n_in,
                              void* d_out, int out_size)
{
    const float* hs      = (const float*)d_in[0];
    const float* W_in    = (const float*)d_in[1];
    const float* conv_w  = (const float*)d_in[2];
    const float* conv_b  = (const float*)d_in[3];
    const float* dt_bias = (const float*)d_in[4];
    const float* A_log   = (const float*)d_in[5];
    const float* D_skip  = (const float*)d_in[6];
    const float* W_out   = (const float*)d_in[7];
    float* out = (float*)d_out;

    gemm1_kernel<<<dim3(25, 64), 256>>>(hs, W_in);
    conv_kernel<<<NROWS / 8 * 2048 / 256, 256>>>(conv_w, conv_b, dt_bias, A_log);
    cumsum_kernel<<<256, 256>>>();
    gscore_kernel<<<dim3(2, 2, 128), 256>>>();   // launch #4 -> ncu capture slot
    pstate_kernel<<<2048, 256>>>();
    carry_kernel<<<64, 256>>>();
    yout_kernel<<<2048, 256>>>(D_skip);
    gemm2_kernel<<<dim3(4, 64), 256>>>(W_out, hs);
    rms_kernel<<<NROWS / 8, 256>>>(out);
}